// round 2
// baseline (speedup 1.0000x reference)
#include <cuda_runtime.h>
#include <math.h>

#define N_TOK   65536
#define DIM     256
#define KCODES  1024
#define LAYERS  8
#define BM      128
#define BN      128
#define KC      32
#define AS      132     // smem row stride (words) for At (residual, transposed [d][m])
#define BSTR    132     // smem row stride for Bs (codebook chunk, transposed [d][code])
#define THREADS 256

// ---------------- device globals (scratch; no allocation allowed) ----------------
__device__ double       g_loss[LAYERS];            // sum of (r - q)^2 per layer
__device__ unsigned int g_counts[LAYERS * KCODES]; // histogram per layer
__device__ float        g_esq[LAYERS * KCODES];    // ||codebook row||^2

// ---------------- init: zero accumulators (must happen every replay) -------------
__global__ void rvq_init_kernel() {
    int t = blockIdx.x * blockDim.x + threadIdx.x;
    if (t < LAYERS) g_loss[t] = 0.0;
    for (int i = t; i < LAYERS * KCODES; i += blockDim.x * gridDim.x)
        g_counts[i] = 0u;
}

// ---------------- codebook norms -------------------------------------------------
__global__ void rvq_esq_kernel(const float* __restrict__ cb) {
    int k = blockIdx.x * blockDim.x + threadIdx.x;  // 0..8191
    if (k >= LAYERS * KCODES) return;
    const float* row = cb + (size_t)k * DIM;
    double s = 0.0;
    #pragma unroll 4
    for (int d = 0; d < DIM; d++) { double v = (double)row[d]; s += v * v; }
    g_esq[k] = (float)s;
}

// ---------------- main fused kernel ----------------------------------------------
// One block = 128 tokens, residual lives in smem (transposed) across all 8 layers.
extern __shared__ float smem_dyn[];

__global__ __launch_bounds__(THREADS, 1)
void rvq_main_kernel(const float* __restrict__ z,
                     const float* __restrict__ codebooks,
                     float* __restrict__ out)
{
    float* At    = smem_dyn;                 // DIM * AS      = 33792 words
    float* Bs    = At + DIM * AS;            // KC * BSTR     =  4224 words
    float* sE    = Bs + KC * BSTR;           // KCODES        =  1024
    float* sZsq  = sE + KCODES;              // BM            =   128
    float* sPart = sZsq + BM;                // THREADS       =   256
    int*   sIdx  = (int*)(sPart + THREADS);  // BM            =   128
    float* sLoss = (float*)(sIdx + BM);      // 1

    const int tid = threadIdx.x;
    const int tx  = tid & 15;
    const int ty  = tid >> 4;
    const int m0  = blockIdx.x * BM;
    const float* zblk = z + (size_t)m0 * DIM;

    // ---- load residual = z, transposed into smem (coalesced global reads) ----
    for (int i = tid; i < BM * DIM; i += THREADS) {
        int m = i >> 8;            // token within block
        int d = i & 255;           // dim (lanes vary d -> coalesced)
        At[d * AS + m] = zblk[i];
    }
    __syncthreads();

    // ---- initial per-token ||r||^2 ----
    {
        int m = tid & 127, h = tid >> 7;
        float s = 0.f;
        #pragma unroll 8
        for (int dd = 0; dd < 128; dd++) {
            float v = At[(h * 128 + dd) * AS + m];
            s += v * v;
        }
        sPart[tid] = s;
    }
    __syncthreads();
    if (tid < BM) sZsq[tid] = sPart[tid] + sPart[tid + BM];
    __syncthreads();

    // ======================= layer loop =======================
    for (int l = 0; l < LAYERS; l++) {
        const float* cb = codebooks + (size_t)l * KCODES * DIM;

        for (int i = tid; i < KCODES; i += THREADS)
            sE[i] = g_esq[l * KCODES + i];
        if (tid == 0) *sLoss = 0.f;
        __syncthreads();

        // per-thread row z_sq (rows split 4+4 for conflict-free LDS.128)
        float zr[8];
        #pragma unroll
        for (int i = 0; i < 8; i++) {
            int r = (i < 4) ? (ty * 4 + i) : (64 + ty * 4 + i - 4);
            zr[i] = sZsq[r];
        }

        float best[8];
        int   bidx[8];
        #pragma unroll
        for (int i = 0; i < 8; i++) { best[i] = 3.4e38f; bidx[i] = 0; }

        for (int n0 = 0; n0 < KCODES; n0 += BN) {
            float acc[8][8];
            #pragma unroll
            for (int i = 0; i < 8; i++)
                #pragma unroll
                for (int j = 0; j < 8; j++) acc[i][j] = 0.f;

            for (int d0 = 0; d0 < DIM; d0 += KC) {
                // load Bs: codes [n0, n0+128), dims [d0, d0+32), transposed
                #pragma unroll
                for (int it = 0; it < 4; it++) {
                    int f4  = tid + it * THREADS;       // 0..1023
                    int row = f4 & 127;                  // code (lanes vary row)
                    int c4  = f4 >> 7;                   // 0..7
                    const float4 v = *(const float4*)(cb + (size_t)(n0 + row) * DIM + d0 + c4 * 4);
                    Bs[(c4 * 4 + 0) * BSTR + row] = v.x;
                    Bs[(c4 * 4 + 1) * BSTR + row] = v.y;
                    Bs[(c4 * 4 + 2) * BSTR + row] = v.z;
                    Bs[(c4 * 4 + 3) * BSTR + row] = v.w;
                }
                __syncthreads();

                #pragma unroll 8
                for (int kk = 0; kk < KC; kk++) {
                    const float4 a0 = *(const float4*)(At + (d0 + kk) * AS + ty * 4);
                    const float4 a1 = *(const float4*)(At + (d0 + kk) * AS + 64 + ty * 4);
                    const float4 b0 = *(const float4*)(Bs + kk * BSTR + tx * 4);
                    const float4 b1 = *(const float4*)(Bs + kk * BSTR + 64 + tx * 4);
                    float av[8] = {a0.x, a0.y, a0.z, a0.w, a1.x, a1.y, a1.z, a1.w};
                    float bv[8] = {b0.x, b0.y, b0.z, b0.w, b1.x, b1.y, b1.z, b1.w};
                    #pragma unroll
                    for (int i = 0; i < 8; i++)
                        #pragma unroll
                        for (int j = 0; j < 8; j++)
                            acc[i][j] = fmaf(av[i], bv[j], acc[i][j]);
                }
                __syncthreads();
            }

            // epilogue: distance + running argmin (replicates reference rounding:
            // t1 = fl(z_sq + e_sq); s = fl(t1 - 2*dot) via single-round FMA)
            #pragma unroll
            for (int j = 0; j < 8; j++) {
                int c    = (j < 4) ? (tx * 4 + j) : (64 + tx * 4 + j - 4);
                int kidx = n0 + c;
                float e  = sE[kidx];
                #pragma unroll
                for (int i = 0; i < 8; i++) {
                    float t1 = zr[i] + e;
                    float s  = fmaf(-2.0f, acc[i][j], t1);
                    if (s < best[i]) { best[i] = s; bidx[i] = kidx; }
                }
            }
        }

        // cross-thread argmin over tx (16 lanes share a half-warp), lowest-index ties
        #pragma unroll
        for (int off = 8; off >= 1; off >>= 1) {
            #pragma unroll
            for (int i = 0; i < 8; i++) {
                float ov = __shfl_down_sync(0xffffffffu, best[i], off, 16);
                int   oi = __shfl_down_sync(0xffffffffu, bidx[i], off, 16);
                if (ov < best[i] || (ov == best[i] && oi < bidx[i])) {
                    best[i] = ov; bidx[i] = oi;
                }
            }
        }
        if (tx == 0) {
            #pragma unroll
            for (int i = 0; i < 8; i++) {
                int r = (i < 4) ? (ty * 4 + i) : (64 + ty * 4 + i - 4);
                sIdx[r] = bidx[i];
            }
        }
        __syncthreads();

        // ---- residual update + losses (straight-through rounding replicated) ----
        {
            int m = tid & 127, h = tid >> 7;
            int idx = sIdx[m];
            const float4* crow = (const float4*)(cb + (size_t)idx * DIM);
            float lss = 0.f, zs = 0.f;
            #pragma unroll 4
            for (int q4 = 0; q4 < 32; q4++) {
                int d4 = h * 32 + q4;
                float4 c = crow[d4];
                float cv[4] = {c.x, c.y, c.z, c.w};
                #pragma unroll
                for (int u = 0; u < 4; u++) {
                    int d = d4 * 4 + u;
                    float r    = At[d * AS + m];
                    float q    = cv[u];
                    float diff = r - q;              // loss uses raw quantized
                    float qst  = r + (q - r);        // straight-through value
                    float rn   = r - qst;            // reference residual update
                    At[d * AS + m] = rn;
                    lss += diff * diff;
                    zs  += rn * rn;
                }
            }
            sPart[tid] = zs;
            #pragma unroll
            for (int off = 16; off; off >>= 1)
                lss += __shfl_down_sync(0xffffffffu, lss, off);
            if ((tid & 31) == 0) atomicAdd(sLoss, lss);
        }
        __syncthreads();

        if (tid < BM) {
            sZsq[tid] = sPart[tid] + sPart[tid + BM];
            int idx = sIdx[tid];
            atomicAdd(&g_counts[l * KCODES + idx], 1u);
            out[(size_t)N_TOK * DIM + (size_t)l * N_TOK + m0 + tid] = (float)idx;
        }
        if (tid == 0) atomicAdd(&g_loss[l], (double)(*sLoss));
        __syncthreads();
    }

    // ---- quantized_sum = z - residual_final ----
    for (int i = tid; i < BM * DIM; i += THREADS) {
        int m = i >> 8;
        int d = i & 255;
        out[(size_t)(m0 + m) * DIM + d] = zblk[i] - At[d * AS + m];
    }
}

// ---------------- finalize: perplexity + scalar losses ---------------------------
__global__ void rvq_final_kernel(float* __restrict__ out) {
    __shared__ double red[8];
    int t = threadIdx.x;   // 256 threads, 1 block
    double total_perp = 0.0;

    for (int l = 0; l < LAYERS; l++) {
        double local = 0.0;
        for (int k = t; k < KCODES; k += 256) {
            float p = (float)g_counts[l * KCODES + k] / (float)N_TOK;
            local += (double)(p * logf(p + 1e-10f));
        }
        #pragma unroll
        for (int off = 16; off; off >>= 1)
            local += __shfl_down_sync(0xffffffffu, local, off);
        if ((t & 31) == 0) red[t >> 5] = local;
        __syncthreads();
        if (t == 0) {
            double s = 0.0;
            for (int w = 0; w < 8; w++) s += red[w];
            total_perp += exp(-s);
        }
        __syncthreads();
    }

    if (t == 0) {
        double tc = 0.0;
        for (int l = 0; l < LAYERS; l++)
            tc += g_loss[l] / ((double)N_TOK * (double)DIM);
        size_t off = (size_t)N_TOK * DIM + (size_t)LAYERS * N_TOK;
        out[off + 0] = (float)(0.25 * tc + tc);     // vq_loss
        out[off + 1] = (float)tc;                   // total_commit
        out[off + 2] = (float)tc;                   // total_cb (== commit numerically)
        out[off + 3] = (float)(total_perp / (double)LAYERS);
    }
}

// ---------------- launch ----------------------------------------------------------
extern "C" void kernel_launch(void* const* d_in, const int* in_sizes, int n_in,
                              void* d_out, int out_size) {
    const float* z  = (const float*)d_in[0];
    const float* cb = (const float*)d_in[1];
    float* out = (float*)d_out;

    const int smem_bytes =
        (DIM * AS + KC * BSTR + KCODES + BM + THREADS + BM + 8) * (int)sizeof(float);

    cudaFuncSetAttribute(rvq_main_kernel,
                         cudaFuncAttributeMaxDynamicSharedMemorySize, smem_bytes);

    rvq_init_kernel<<<1, 256>>>();
    rvq_esq_kernel<<<(LAYERS * KCODES + 255) / 256, 256>>>(cb);
    rvq_main_kernel<<<N_TOK / BM, THREADS, smem_bytes>>>(z, cb, out);
    rvq_final_kernel<<<1, 256>>>(out);
}

// round 3
// speedup vs baseline: 1.0000x; 1.0000x over previous
#include <cuda_runtime.h>
#include <math.h>

#define N_TOK   65536
#define DIM     256
#define KCODES  1024
#define LAYERS  8
#define BM      128
#define BN      128
#define KC      32
#define AS      132     // smem row stride (words) for At (residual, transposed [d][m])
#define BSTR    132     // smem row stride for Bs (codebook chunk, transposed [d][code])
#define THREADS 256

// ---------------- device globals (scratch; no allocation allowed) ----------------
__device__ double       g_loss[LAYERS];            // sum of (r - q)^2 per layer
__device__ unsigned int g_counts[LAYERS * KCODES]; // histogram per layer
__device__ float        g_esq[LAYERS * KCODES];    // ||codebook row||^2

// ---------------- init: zero accumulators (must happen every replay) -------------
__global__ void rvq_init_kernel() {
    int t = blockIdx.x * blockDim.x + threadIdx.x;
    if (t < LAYERS) g_loss[t] = 0.0;
    for (int i = t; i < LAYERS * KCODES; i += blockDim.x * gridDim.x)
        g_counts[i] = 0u;
}

// ---------------- codebook norms -------------------------------------------------
__global__ void rvq_esq_kernel(const float* __restrict__ cb) {
    int k = blockIdx.x * blockDim.x + threadIdx.x;  // 0..8191
    if (k >= LAYERS * KCODES) return;
    const float* row = cb + (size_t)k * DIM;
    double s = 0.0;
    #pragma unroll 4
    for (int d = 0; d < DIM; d++) { double v = (double)row[d]; s += v * v; }
    g_esq[k] = (float)s;
}

// ---------------- main fused kernel ----------------------------------------------
// One block = 128 tokens, residual lives in smem (transposed) across all 8 layers.
extern __shared__ float smem_dyn[];

__global__ __launch_bounds__(THREADS, 1)
void rvq_main_kernel(const float* __restrict__ z,
                     const float* __restrict__ codebooks,
                     float* __restrict__ out)
{
    float* At    = smem_dyn;                 // DIM * AS      = 33792 words
    float* Bs    = At + DIM * AS;            // KC * BSTR     =  4224 words
    float* sE    = Bs + KC * BSTR;           // KCODES        =  1024
    float* sZsq  = sE + KCODES;              // BM            =   128
    float* sPart = sZsq + BM;                // THREADS       =   256
    int*   sIdx  = (int*)(sPart + THREADS);  // BM            =   128
    float* sLoss = (float*)(sIdx + BM);      // 1

    const int tid = threadIdx.x;
    const int tx  = tid & 15;
    const int ty  = tid >> 4;
    const int m0  = blockIdx.x * BM;
    const float* zblk = z + (size_t)m0 * DIM;

    // ---- load residual = z, transposed into smem (coalesced global reads) ----
    for (int i = tid; i < BM * DIM; i += THREADS) {
        int m = i >> 8;            // token within block
        int d = i & 255;           // dim (lanes vary d -> coalesced)
        At[d * AS + m] = zblk[i];
    }
    __syncthreads();

    // ---- initial per-token ||r||^2 ----
    {
        int m = tid & 127, h = tid >> 7;
        float s = 0.f;
        #pragma unroll 8
        for (int dd = 0; dd < 128; dd++) {
            float v = At[(h * 128 + dd) * AS + m];
            s += v * v;
        }
        sPart[tid] = s;
    }
    __syncthreads();
    if (tid < BM) sZsq[tid] = sPart[tid] + sPart[tid + BM];
    __syncthreads();

    // ======================= layer loop =======================
    for (int l = 0; l < LAYERS; l++) {
        const float* cb = codebooks + (size_t)l * KCODES * DIM;

        for (int i = tid; i < KCODES; i += THREADS)
            sE[i] = g_esq[l * KCODES + i];
        if (tid == 0) *sLoss = 0.f;
        __syncthreads();

        // per-thread row z_sq (rows split 4+4 for conflict-free LDS.128)
        float zr[8];
        #pragma unroll
        for (int i = 0; i < 8; i++) {
            int r = (i < 4) ? (ty * 4 + i) : (64 + ty * 4 + i - 4);
            zr[i] = sZsq[r];
        }

        float best[8];
        int   bidx[8];
        #pragma unroll
        for (int i = 0; i < 8; i++) { best[i] = 3.4e38f; bidx[i] = 0; }

        for (int n0 = 0; n0 < KCODES; n0 += BN) {
            float acc[8][8];
            #pragma unroll
            for (int i = 0; i < 8; i++)
                #pragma unroll
                for (int j = 0; j < 8; j++) acc[i][j] = 0.f;

            for (int d0 = 0; d0 < DIM; d0 += KC) {
                // load Bs: codes [n0, n0+128), dims [d0, d0+32), transposed
                #pragma unroll
                for (int it = 0; it < 4; it++) {
                    int f4  = tid + it * THREADS;       // 0..1023
                    int row = f4 & 127;                  // code (lanes vary row)
                    int c4  = f4 >> 7;                   // 0..7
                    const float4 v = *(const float4*)(cb + (size_t)(n0 + row) * DIM + d0 + c4 * 4);
                    Bs[(c4 * 4 + 0) * BSTR + row] = v.x;
                    Bs[(c4 * 4 + 1) * BSTR + row] = v.y;
                    Bs[(c4 * 4 + 2) * BSTR + row] = v.z;
                    Bs[(c4 * 4 + 3) * BSTR + row] = v.w;
                }
                __syncthreads();

                #pragma unroll 8
                for (int kk = 0; kk < KC; kk++) {
                    const float4 a0 = *(const float4*)(At + (d0 + kk) * AS + ty * 4);
                    const float4 a1 = *(const float4*)(At + (d0 + kk) * AS + 64 + ty * 4);
                    const float4 b0 = *(const float4*)(Bs + kk * BSTR + tx * 4);
                    const float4 b1 = *(const float4*)(Bs + kk * BSTR + 64 + tx * 4);
                    float av[8] = {a0.x, a0.y, a0.z, a0.w, a1.x, a1.y, a1.z, a1.w};
                    float bv[8] = {b0.x, b0.y, b0.z, b0.w, b1.x, b1.y, b1.z, b1.w};
                    #pragma unroll
                    for (int i = 0; i < 8; i++)
                        #pragma unroll
                        for (int j = 0; j < 8; j++)
                            acc[i][j] = fmaf(av[i], bv[j], acc[i][j]);
                }
                __syncthreads();
            }

            // epilogue: distance + running argmin (replicates reference rounding:
            // t1 = fl(z_sq + e_sq); s = fl(t1 - 2*dot) via single-round FMA)
            #pragma unroll
            for (int j = 0; j < 8; j++) {
                int c    = (j < 4) ? (tx * 4 + j) : (64 + tx * 4 + j - 4);
                int kidx = n0 + c;
                float e  = sE[kidx];
                #pragma unroll
                for (int i = 0; i < 8; i++) {
                    float t1 = zr[i] + e;
                    float s  = fmaf(-2.0f, acc[i][j], t1);
                    if (s < best[i]) { best[i] = s; bidx[i] = kidx; }
                }
            }
        }

        // cross-thread argmin over tx (16 lanes share a half-warp), lowest-index ties
        #pragma unroll
        for (int off = 8; off >= 1; off >>= 1) {
            #pragma unroll
            for (int i = 0; i < 8; i++) {
                float ov = __shfl_down_sync(0xffffffffu, best[i], off, 16);
                int   oi = __shfl_down_sync(0xffffffffu, bidx[i], off, 16);
                if (ov < best[i] || (ov == best[i] && oi < bidx[i])) {
                    best[i] = ov; bidx[i] = oi;
                }
            }
        }
        if (tx == 0) {
            #pragma unroll
            for (int i = 0; i < 8; i++) {
                int r = (i < 4) ? (ty * 4 + i) : (64 + ty * 4 + i - 4);
                sIdx[r] = bidx[i];
            }
        }
        __syncthreads();

        // ---- residual update + losses (straight-through rounding replicated) ----
        {
            int m = tid & 127, h = tid >> 7;
            int idx = sIdx[m];
            const float4* crow = (const float4*)(cb + (size_t)idx * DIM);
            float lss = 0.f, zs = 0.f;
            #pragma unroll 4
            for (int q4 = 0; q4 < 32; q4++) {
                int d4 = h * 32 + q4;
                float4 c = crow[d4];
                float cv[4] = {c.x, c.y, c.z, c.w};
                #pragma unroll
                for (int u = 0; u < 4; u++) {
                    int d = d4 * 4 + u;
                    float r    = At[d * AS + m];
                    float q    = cv[u];
                    float diff = r - q;              // loss uses raw quantized
                    float qst  = r + (q - r);        // straight-through value
                    float rn   = r - qst;            // reference residual update
                    At[d * AS + m] = rn;
                    lss += diff * diff;
                    zs  += rn * rn;
                }
            }
            sPart[tid] = zs;
            #pragma unroll
            for (int off = 16; off; off >>= 1)
                lss += __shfl_down_sync(0xffffffffu, lss, off);
            if ((tid & 31) == 0) atomicAdd(sLoss, lss);
        }
        __syncthreads();

        if (tid < BM) {
            sZsq[tid] = sPart[tid] + sPart[tid + BM];
            int idx = sIdx[tid];
            atomicAdd(&g_counts[l * KCODES + idx], 1u);
            out[(size_t)N_TOK * DIM + (size_t)l * N_TOK + m0 + tid] = (float)idx;
        }
        if (tid == 0) atomicAdd(&g_loss[l], (double)(*sLoss));
        __syncthreads();
    }

    // ---- quantized_sum = z - residual_final ----
    for (int i = tid; i < BM * DIM; i += THREADS) {
        int m = i >> 8;
        int d = i & 255;
        out[(size_t)(m0 + m) * DIM + d] = zblk[i] - At[d * AS + m];
    }
}

// ---------------- finalize: perplexity + scalar losses ---------------------------
__global__ void rvq_final_kernel(float* __restrict__ out) {
    __shared__ double red[8];
    int t = threadIdx.x;   // 256 threads, 1 block
    double total_perp = 0.0;

    for (int l = 0; l < LAYERS; l++) {
        double local = 0.0;
        for (int k = t; k < KCODES; k += 256) {
            float p = (float)g_counts[l * KCODES + k] / (float)N_TOK;
            local += (double)(p * logf(p + 1e-10f));
        }
        #pragma unroll
        for (int off = 16; off; off >>= 1)
            local += __shfl_down_sync(0xffffffffu, local, off);
        if ((t & 31) == 0) red[t >> 5] = local;
        __syncthreads();
        if (t == 0) {
            double s = 0.0;
            for (int w = 0; w < 8; w++) s += red[w];
            total_perp += exp(-s);
        }
        __syncthreads();
    }

    if (t == 0) {
        double tc = 0.0;
        for (int l = 0; l < LAYERS; l++)
            tc += g_loss[l] / ((double)N_TOK * (double)DIM);
        size_t off = (size_t)N_TOK * DIM + (size_t)LAYERS * N_TOK;
        out[off + 0] = (float)(0.25 * tc + tc);     // vq_loss
        out[off + 1] = (float)tc;                   // total_commit
        out[off + 2] = (float)tc;                   // total_cb (== commit numerically)
        out[off + 3] = (float)(total_perp / (double)LAYERS);
    }
}

// ---------------- launch ----------------------------------------------------------
extern "C" void kernel_launch(void* const* d_in, const int* in_sizes, int n_in,
                              void* d_out, int out_size) {
    const float* z  = (const float*)d_in[0];
    const float* cb = (const float*)d_in[1];
    float* out = (float*)d_out;

    const int smem_bytes =
        (DIM * AS + KC * BSTR + KCODES + BM + THREADS + BM + 8) * (int)sizeof(float);

    cudaFuncSetAttribute(rvq_main_kernel,
                         cudaFuncAttributeMaxDynamicSharedMemorySize, smem_bytes);

    rvq_init_kernel<<<1, 256>>>();
    rvq_esq_kernel<<<(LAYERS * KCODES + 255) / 256, 256>>>(cb);
    rvq_main_kernel<<<N_TOK / BM, THREADS, smem_bytes>>>(z, cb, out);
    rvq_final_kernel<<<1, 256>>>(out);
}

// round 7
// speedup vs baseline: 1.5918x; 1.5918x over previous
#include <cuda_runtime.h>
#include <cuda_bf16.h>
#include <math.h>
#include <stdint.h>

#define N_TOK   65536
#define DIM     256
#define KCODES  1024
#define LAYERS  8
#define THREADS 256
#define NT_TILES 512          // 8 layers * 8 nchunks * 4 dchunks * 2 splits
#define BROW    144           // B smem row bytes: 64 dims*2B + 16B pad
#define BSTAGE  (128*BROW)    // 18432 B per stage
#define AROW    528           // A smem row bytes: 264 bf16 (256 + 8 pad)
#define AROWU   132           // A row stride in u32
#define TIE_EPS 2e-3f

// smem byte offsets
#define SM_AH    0
#define SM_AL    (SM_AH + 128*AROW)          // 67584
#define SM_B     (SM_AL + 128*AROW)          // 135168
#define SM_SE    (SM_B + 4*BSTAGE)           // 208896
#define SM_ZSQ   (SM_SE + 4096)              // 212992
#define SM_PART  (SM_ZSQ + 512)              // 213504
#define SM_RV1   (SM_PART + 1024)            // 214528
#define SM_RI1   (SM_RV1 + 1024)             // 215552
#define SM_RV2   (SM_RI1 + 1024)             // 216576
#define SM_RI2   (SM_RV2 + 1024)             // 217600
#define SM_IDX   (SM_RI2 + 1024)             // 218624
#define SM_FLAG  (SM_IDX + 512)              // 219136
#define SM_NFL   (SM_FLAG + 512)             // 219648
#define SM_TOTAL (SM_NFL + 16)               // 219664

// ---------------- device globals ----------------
__device__ double        g_loss[LAYERS];
__device__ unsigned int  g_counts[LAYERS * KCODES];
__device__ float         g_esq[LAYERS * KCODES];
__device__ __nv_bfloat16 g_cbh[LAYERS * KCODES * DIM];
__device__ __nv_bfloat16 g_cbl[LAYERS * KCODES * DIM];
__device__ float         g_resid[(size_t)N_TOK * DIM];   // EXACT fp32 residual chain

// ---------------- helpers ----------------
__device__ __forceinline__ uint32_t smem_u32p(const void* p) {
    uint32_t a;
    asm("{ .reg .u64 t; cvta.to.shared.u64 t, %1; cvt.u32.u64 %0, t; }" : "=r"(a) : "l"(p));
    return a;
}
__device__ __forceinline__ float ulo(uint32_t u) { return __uint_as_float(u << 16); }
__device__ __forceinline__ float uhi(uint32_t u) { return __uint_as_float(u & 0xffff0000u); }
__device__ __forceinline__ uint32_t b2u(float v) {
    return (uint32_t)__bfloat16_as_ushort(__float2bfloat16(v));
}
__device__ __forceinline__ void split2p(float v0, float v1, uint32_t& h, uint32_t& l) {
    uint32_t h0 = b2u(v0), h1 = b2u(v1);
    float r0 = v0 - ulo(h0), r1 = v1 - ulo(h1);
    h = h0 | (h1 << 16);
    l = b2u(r0) | (b2u(r1) << 16);
}

__device__ __forceinline__ void ldsm_x4(uint32_t* r, uint32_t addr) {
    asm volatile("ldmatrix.sync.aligned.m8n8.x4.shared.b16 {%0,%1,%2,%3}, [%4];"
        : "=r"(r[0]), "=r"(r[1]), "=r"(r[2]), "=r"(r[3]) : "r"(addr));
}
__device__ __forceinline__ void mma16816(float* c, const uint32_t* a, uint32_t b0, uint32_t b1) {
    asm volatile("mma.sync.aligned.m16n8k16.row.col.f32.bf16.bf16.f32 "
        "{%0,%1,%2,%3}, {%4,%5,%6,%7}, {%8,%9}, {%0,%1,%2,%3};"
        : "+f"(c[0]), "+f"(c[1]), "+f"(c[2]), "+f"(c[3])
        : "r"(a[0]), "r"(a[1]), "r"(a[2]), "r"(a[3]), "r"(b0), "r"(b1));
}
#define CP16(dst, src) asm volatile("cp.async.cg.shared.global [%0], [%1], 16;" :: "r"(dst), "l"(src))
#define CP_COMMIT()    asm volatile("cp.async.commit_group;" ::: "memory")
#define CP_WAIT2()     asm volatile("cp.async.wait_group 2;" ::: "memory")

// top-2 insert (ascending scan order -> strict < keeps lowest index on ties)
__device__ __forceinline__ void top2_ins(float v, int c, float& b1, int& i1, float& b2, int& i2) {
    if (v < b2) {
        if (v < b1) { b2 = b1; i2 = i1; b1 = v; i1 = c; }
        else        { b2 = v; i2 = c; }
    }
}
__device__ __forceinline__ void top2_merge(float& b1, int& i1, float& b2, int& i2,
                                           float o1, int oi1, float o2, int oi2) {
    bool oless = (o1 < b1) || (o1 == b1 && oi1 < i1);
    float w1 = oless ? o1 : b1;  int wi1 = oless ? oi1 : i1;
    float lv = oless ? b1 : o1;  int li  = oless ? i1  : oi1;
    float sv = oless ? o2 : b2;  int si  = oless ? oi2 : i2;
    bool sless = (sv < lv) || (sv == lv && si < li);
    b1 = w1; i1 = wi1;
    b2 = sless ? sv : lv; i2 = sless ? si : li;
}

// ---------------- prep kernels ----------------
__global__ void rvq_init_kernel() {
    int t = blockIdx.x * blockDim.x + threadIdx.x;
    if (t < LAYERS) g_loss[t] = 0.0;
    for (int i = t; i < LAYERS * KCODES; i += blockDim.x * gridDim.x) g_counts[i] = 0u;
}

__global__ void rvq_prep_kernel(const float* __restrict__ cb) {
    int w = (blockIdx.x * blockDim.x + threadIdx.x) >> 5;
    int lane = threadIdx.x & 31;
    if (w >= LAYERS * KCODES) return;
    const float* row = cb + (size_t)w * DIM;
    __nv_bfloat16* ph = g_cbh + (size_t)w * DIM;
    __nv_bfloat16* pl = g_cbl + (size_t)w * DIM;
    double s = 0.0;
    #pragma unroll
    for (int j = 0; j < 8; j++) {
        int d = lane + 32 * j;
        float v = row[d];
        s += (double)v * (double)v;
        __nv_bfloat16 hb = __float2bfloat16(v);
        ph[d] = hb;
        pl[d] = __float2bfloat16(v - __bfloat162float(hb));
    }
    #pragma unroll
    for (int off = 16; off; off >>= 1) s += __shfl_down_sync(0xffffffffu, s, off);
    if (lane == 0) g_esq[w] = (float)s;
}

// ---------------- main kernel ----------------
extern __shared__ char smc[];

__global__ __launch_bounds__(THREADS, 1)
void rvq_main_kernel(const float* __restrict__ z,
                     const float* __restrict__ codebooks,
                     float* __restrict__ out)
{
    const int tid  = threadIdx.x;
    const int lane = tid & 31;
    const int wid  = tid >> 5;
    const int wm   = wid & 3;
    const int wn   = wid >> 2;
    const int m0   = blockIdx.x * 128;

    const uint32_t sb = smem_u32p(smc);
    uint32_t* AhU = (uint32_t*)(smc + SM_AH);
    uint32_t* AlU = (uint32_t*)(smc + SM_AL);
    float*  sE    = (float*)(smc + SM_SE);
    float*  sZsq  = (float*)(smc + SM_ZSQ);
    float*  sPart = (float*)(smc + SM_PART);
    float*  sRV1  = (float*)(smc + SM_RV1);
    int*    sRI1  = (int*)(smc + SM_RI1);
    float*  sRV2  = (float*)(smc + SM_RV2);
    int*    sRI2  = (int*)(smc + SM_RI2);
    int*    sIdx  = (int*)(smc + SM_IDX);
    int*    sFlag = (int*)(smc + SM_FLAG);
    int*    sNFl  = (int*)(smc + SM_NFL);

    const int g  = lane >> 3, lr = lane & 7;
    const int rofs = lr + (g & 1) * 8;
    const int kofs = (g >> 1) * 8;
    const uint32_t aA_base  = sb + SM_AH + (uint32_t)(wm * 32 + rofs) * AROW + kofs * 2;
    const uint32_t aAl_base = sb + SM_AL + (uint32_t)(wm * 32 + rofs) * AROW + kofs * 2;
    const uint32_t aB_lane  = (uint32_t)(wn * 64 + rofs) * BROW + kofs * 2;

    auto produce = [&](int t) {
        int pl8 = t >> 6, pnc = (t >> 3) & 7, pdc = (t >> 1) & 3, psp = t & 1;
        const __nv_bfloat16* base = psp ? g_cbl : g_cbh;
        const __nv_bfloat16* src0 = base + ((size_t)(pl8 * KCODES + pnc * 128) * DIM) + pdc * 64;
        uint32_t dst0 = sb + SM_B + (uint32_t)(t & 3) * BSTAGE;
        #pragma unroll
        for (int i = 0; i < 4; i++) {
            int id = tid + 256 * i;
            int row = id >> 3, c = id & 7;
            CP16(dst0 + (uint32_t)row * BROW + c * 16, src0 + (size_t)row * DIM + c * 8);
        }
    };

    produce(0); CP_COMMIT();
    produce(1); CP_COMMIT();
    produce(2); CP_COMMIT();

    // split z into Ah/Al, zsq via serial ascending fmaf chain (R2 ordering)
    {
        int mtk = tid >> 1, hb = tid & 1;
        const float4* zrow = (const float4*)(z + (size_t)(m0 + mtk) * DIM + hb * 128);
        float zs = 0.f;
        #pragma unroll 8
        for (int j4 = 0; j4 < 32; j4++) {
            float4 v = zrow[j4];
            zs = fmaf(v.x, v.x, zs); zs = fmaf(v.y, v.y, zs);
            zs = fmaf(v.z, v.z, zs); zs = fmaf(v.w, v.w, zs);
            uint32_t h0, l0, h1, l1;
            split2p(v.x, v.y, h0, l0);
            split2p(v.z, v.w, h1, l1);
            uint32_t pa = (uint32_t)mtk * AROWU + hb * 64 + j4 * 2;
            AhU[pa] = h0; AhU[pa + 1] = h1;
            AlU[pa] = l0; AlU[pa + 1] = l1;
        }
        sPart[tid] = zs;
    }
    for (int i = tid; i < KCODES; i += THREADS) sE[i] = g_esq[i];
    __syncthreads();
    if (tid < 128) sZsq[tid] = sPart[2 * tid] + sPart[2 * tid + 1];
    __syncthreads();

    int tcur = 0;
    for (int lay = 0; lay < LAYERS; lay++) {
        // exact residual source for this layer (z for layer 0, scratch after)
        const float* rl = (lay == 0) ? z : g_resid;

        float zq[4];
        #pragma unroll
        for (int s = 0; s < 4; s++)
            zq[s] = sZsq[wm * 32 + (s >> 1) * 16 + (s & 1) * 8 + (lane >> 2)];
        float b1[4] = {3.4e38f, 3.4e38f, 3.4e38f, 3.4e38f};
        float b2[4] = {3.4e38f, 3.4e38f, 3.4e38f, 3.4e38f};
        int   i1[4] = {0, 0, 0, 0};
        int   i2[4] = {0, 0, 0, 0};
        if (tid == 0) *sNFl = 0;

        for (int nc = 0; nc < 8; nc++) {
            float acc[2][8][4];
            #pragma unroll
            for (int ma = 0; ma < 2; ma++)
                #pragma unroll
                for (int na = 0; na < 8; na++)
                    #pragma unroll
                    for (int v = 0; v < 4; v++) acc[ma][na][v] = 0.f;

            for (int dc = 0; dc < 4; dc++) {
                for (int sp = 0; sp < 2; sp++) {
                    CP_WAIT2();
                    __syncthreads();
                    if (tcur + 3 < NT_TILES) { produce(tcur + 3); CP_COMMIT(); }
                    uint32_t bst = sb + SM_B + (uint32_t)(tcur & 3) * BSTAGE;
                    #pragma unroll
                    for (int ks = 0; ks < 4; ks++) {
                        int k0 = ks * 16, kA = dc * 64 + k0;
                        uint32_t bf[16];
                        #pragma unroll
                        for (int np = 0; np < 4; np++)
                            ldsm_x4(bf + np * 4, bst + aB_lane + (uint32_t)(np * 16) * BROW + k0 * 2);
                        uint32_t af[4];
                        #pragma unroll
                        for (int ma = 0; ma < 2; ma++) {
                            ldsm_x4(af, aA_base + (uint32_t)(ma * 16) * AROW + kA * 2);
                            #pragma unroll
                            for (int na = 0; na < 8; na++) {
                                int np = na >> 1, o = na & 1;
                                mma16816(acc[ma][na], af, bf[np * 4 + o], bf[np * 4 + o + 2]);
                            }
                        }
                        if (sp == 0) {
                            #pragma unroll
                            for (int ma = 0; ma < 2; ma++) {
                                ldsm_x4(af, aAl_base + (uint32_t)(ma * 16) * AROW + kA * 2);
                                #pragma unroll
                                for (int na = 0; na < 8; na++) {
                                    int np = na >> 1, o = na & 1;
                                    mma16816(acc[ma][na], af, bf[np * 4 + o], bf[np * 4 + o + 2]);
                                }
                            }
                        }
                    }
                    tcur++;
                }
            }

            // epilogue: distances + running top-2 (ascending code order)
            #pragma unroll
            for (int na = 0; na < 8; na++) {
                int cbase = nc * 128 + wn * 64 + na * 8 + (lane & 3) * 2;
                float2 e = *(float2*)&sE[cbase];
                #pragma unroll
                for (int ma = 0; ma < 2; ma++) {
                    float* d = acc[ma][na];
                    int s0 = ma * 2, s1 = ma * 2 + 1;
                    float v0 = fmaf(-2.0f, d[0], zq[s0] + e.x);
                    float v1 = fmaf(-2.0f, d[1], zq[s0] + e.y);
                    top2_ins(v0, cbase,     b1[s0], i1[s0], b2[s0], i2[s0]);
                    top2_ins(v1, cbase + 1, b1[s0], i1[s0], b2[s0], i2[s0]);
                    float w0 = fmaf(-2.0f, d[2], zq[s1] + e.x);
                    float w1 = fmaf(-2.0f, d[3], zq[s1] + e.y);
                    top2_ins(w0, cbase,     b1[s1], i1[s1], b2[s1], i2[s1]);
                    top2_ins(w1, cbase + 1, b1[s1], i1[s1], b2[s1], i2[s1]);
                }
            }
        }

        // cross-lane top-2 merge (4 lanes share a token row)
        #pragma unroll
        for (int off = 1; off <= 2; off <<= 1) {
            #pragma unroll
            for (int s = 0; s < 4; s++) {
                float o1 = __shfl_xor_sync(0xffffffffu, b1[s], off);
                int  oi1 = __shfl_xor_sync(0xffffffffu, i1[s], off);
                float o2 = __shfl_xor_sync(0xffffffffu, b2[s], off);
                int  oi2 = __shfl_xor_sync(0xffffffffu, i2[s], off);
                top2_merge(b1[s], i1[s], b2[s], i2[s], o1, oi1, o2, oi2);
            }
        }
        if ((lane & 3) == 0) {
            #pragma unroll
            for (int s = 0; s < 4; s++) {
                int row = wm * 32 + (s >> 1) * 16 + (s & 1) * 8 + (lane >> 2);
                sRV1[row * 2 + wn] = b1[s]; sRI1[row * 2 + wn] = i1[s];
                sRV2[row * 2 + wn] = b2[s]; sRI2[row * 2 + wn] = i2[s];
            }
        }
        __syncthreads();
        if (tid < 128) {
            float a1 = sRV1[tid * 2], a2 = sRV2[tid * 2];
            int   ai1 = sRI1[tid * 2], ai2 = sRI2[tid * 2];
            top2_merge(a1, ai1, a2, ai2,
                       sRV1[tid * 2 + 1], sRI1[tid * 2 + 1],
                       sRV2[tid * 2 + 1], sRI2[tid * 2 + 1]);
            sIdx[tid] = ai1;
            if (a2 - a1 < TIE_EPS) {
                int p = atomicAdd(sNFl, 1);
                sFlag[p] = tid;
            }
        }
        __syncthreads();

        // -------- exact fp32 arbitration (EXACT residual, R2 serial-fma order) --------
        {
            int nf = *sNFl;
            for (int f = 0; f < nf; f++) {
                int tok = sFlag[f];
                float zqs = sZsq[tok];
                const float4* rrow4 = (const float4*)(rl + (size_t)(m0 + tok) * DIM);
                float lb = 3.4e38f; int li = 0;
                #pragma unroll
                for (int j = 0; j < 4; j++) {
                    int c = tid + 256 * j;
                    const float4* crow = (const float4*)(codebooks +
                        ((size_t)lay * KCODES + c) * DIM);
                    float dot = 0.f;
                    #pragma unroll 8
                    for (int q4 = 0; q4 < 64; q4++) {
                        float4 cv = crow[q4];
                        float4 rv = rrow4[q4];
                        dot = fmaf(rv.x, cv.x, dot);
                        dot = fmaf(rv.y, cv.y, dot);
                        dot = fmaf(rv.z, cv.z, dot);
                        dot = fmaf(rv.w, cv.w, dot);
                    }
                    float dist = fmaf(-2.0f, dot, zqs + g_esq[lay * KCODES + c]);
                    if (dist < lb) { lb = dist; li = c; }
                }
                sRV1[tid] = lb; sRI1[tid] = li;
                __syncthreads();
                for (int stride = 128; stride; stride >>= 1) {
                    if (tid < stride) {
                        float ov = sRV1[tid + stride]; int oi = sRI1[tid + stride];
                        if (ov < sRV1[tid] || (ov == sRV1[tid] && oi < sRI1[tid])) {
                            sRV1[tid] = ov; sRI1[tid] = oi;
                        }
                    }
                    __syncthreads();
                }
                if (tid == 0) sIdx[tok] = sRI1[0];
                __syncthreads();
            }
        }

        if (tid < 128) {
            int idx = sIdx[tid];
            out[(size_t)N_TOK * DIM + (size_t)lay * N_TOK + m0 + tid] = (float)idx;
            atomicAdd(&g_counts[lay * KCODES + idx], 1u);
        }
        __syncthreads();

        // -------- update from EXACT residual; write exact chain + fresh splits --------
        {
            int mtk = tid >> 1, hb = tid & 1;
            int idx = sIdx[mtk];
            size_t tok = (size_t)(m0 + mtk);
            const float4* crow = (const float4*)(codebooks +
                ((size_t)lay * KCODES + idx) * DIM + hb * 128);
            const float4* rrow = (const float4*)(rl + tok * DIM + hb * 128);
            float4* wrow = (float4*)(g_resid + tok * DIM + hb * 128);
            const float4* zrow = (const float4*)(z + tok * DIM + hb * 128);
            float4* orow = (float4*)(out + tok * DIM + hb * 128);
            float lss = 0.f, zs = 0.f;
            #pragma unroll 4
            for (int j4 = 0; j4 < 32; j4++) {
                float4 q = crow[j4];
                float4 r = rrow[j4];
                float d0 = r.x - q.x, d1 = r.y - q.y, d2 = r.z - q.z, d3 = r.w - q.w;
                lss = fmaf(d0, d0, lss); lss = fmaf(d1, d1, lss);
                lss = fmaf(d2, d2, lss); lss = fmaf(d3, d3, lss);
                float n0 = r.x - (r.x + (q.x - r.x));
                float n1 = r.y - (r.y + (q.y - r.y));
                float n2 = r.z - (r.z + (q.z - r.z));
                float n3 = r.w - (r.w + (q.w - r.w));
                if (lay < 7) {
                    zs = fmaf(n0, n0, zs); zs = fmaf(n1, n1, zs);
                    zs = fmaf(n2, n2, zs); zs = fmaf(n3, n3, zs);
                    float4 nw; nw.x = n0; nw.y = n1; nw.z = n2; nw.w = n3;
                    wrow[j4] = nw;
                    uint32_t h0, l0, h1, l1;
                    split2p(n0, n1, h0, l0);
                    split2p(n2, n3, h1, l1);
                    uint32_t pa = (uint32_t)mtk * AROWU + hb * 64 + j4 * 2;
                    AhU[pa] = h0; AhU[pa + 1] = h1;
                    AlU[pa] = l0; AlU[pa + 1] = l1;
                } else {
                    float4 zv = zrow[j4];
                    float4 ov;
                    ov.x = zv.x - n0; ov.y = zv.y - n1; ov.z = zv.z - n2; ov.w = zv.w - n3;
                    orow[j4] = ov;
                }
            }
            sPart[tid] = zs;
            #pragma unroll
            for (int off = 16; off; off >>= 1)
                lss += __shfl_down_sync(0xffffffffu, lss, off);
            if (lane == 0) atomicAdd(&g_loss[lay], (double)lss);
        }
        __syncthreads();
        if (lay < 7) {
            if (tid < 128) sZsq[tid] = sPart[2 * tid] + sPart[2 * tid + 1];
            for (int i = tid; i < KCODES; i += THREADS) sE[i] = g_esq[(lay + 1) * KCODES + i];
            __syncthreads();
        }
    }
}

// ---------------- finalize ----------------
__global__ void rvq_final_kernel(float* __restrict__ out) {
    __shared__ double red[8];
    int t = threadIdx.x;
    double total_perp = 0.0;
    for (int l = 0; l < LAYERS; l++) {
        double local = 0.0;
        for (int k = t; k < KCODES; k += 256) {
            float p = (float)g_counts[l * KCODES + k] / (float)N_TOK;
            local += (double)(p * logf(p + 1e-10f));
        }
        #pragma unroll
        for (int off = 16; off; off >>= 1)
            local += __shfl_down_sync(0xffffffffu, local, off);
        if ((t & 31) == 0) red[t >> 5] = local;
        __syncthreads();
        if (t == 0) {
            double s = 0.0;
            for (int w = 0; w < 8; w++) s += red[w];
            total_perp += exp(-s);
        }
        __syncthreads();
    }
    if (t == 0) {
        double tc = 0.0;
        for (int l = 0; l < LAYERS; l++)
            tc += g_loss[l] / ((double)N_TOK * (double)DIM);
        size_t off = (size_t)N_TOK * DIM + (size_t)LAYERS * N_TOK;
        out[off + 0] = (float)(0.25 * tc + tc);
        out[off + 1] = (float)tc;
        out[off + 2] = (float)tc;
        out[off + 3] = (float)(total_perp / (double)LAYERS);
    }
}

// ---------------- launch ----------------
extern "C" void kernel_launch(void* const* d_in, const int* in_sizes, int n_in,
                              void* d_out, int out_size) {
    const float* z  = (const float*)d_in[0];
    const float* cb = (const float*)d_in[1];
    float* out = (float*)d_out;

    cudaFuncSetAttribute(rvq_main_kernel,
                         cudaFuncAttributeMaxDynamicSharedMemorySize, SM_TOTAL);

    rvq_init_kernel<<<1, 256>>>();
    rvq_prep_kernel<<<(LAYERS * KCODES * 32 + 255) / 256, 256>>>(cb);
    rvq_main_kernel<<<N_TOK / 128, THREADS, SM_TOTAL>>>(z, cb, out);
    rvq_final_kernel<<<1, 256>>>(out);
}

// round 8
// speedup vs baseline: 2.4072x; 1.5122x over previous
#include <cuda_runtime.h>
#include <cuda_bf16.h>
#include <math.h>
#include <stdint.h>

#define N_TOK   65536
#define DIM     256
#define KCODES  1024
#define LAYERS  8
#define THREADS 256
#define NT_TILES 256          // 8 layers * 8 nchunks * 4 dchunks (hi split only)
#define BROW    144           // B smem row bytes: 64 dims*2B + 16B pad
#define BSTAGE  (128*BROW)    // 18432 B per stage
#define AROW    528           // A smem row bytes: 264 bf16 (256 + 8 pad)
#define AROWU   132           // A row stride in u32

// smem byte offsets
#define SM_AH    0
#define SM_B     (SM_AH + 128*AROW)           // 67584
#define SM_SE    (SM_B + 4*BSTAGE)            // 141312
#define SM_ZSQ   (SM_SE + 4096)               // 145408
#define SM_PART  (SM_ZSQ + 512)               // 145920
#define SM_PART2 (SM_PART + 1024)             // 146944
#define SM_MAR   (SM_PART2 + 1024)            // 147968
#define SM_GMIN  (SM_MAR + 512)               // 148480
#define SM_GM2   (SM_GMIN + 512)              // 148992
#define SM_CCNT  (SM_GM2 + 1024)              // 150016
#define SM_FULL  (SM_CCNT + 512)              // 150528
#define SM_CAND  (SM_FULL + 512)              // 151040  u16[128][32]
#define SM_BEST  (SM_CAND + 8192)             // 159232  u64[128]
#define SM_IDX   (SM_BEST + 1024)             // 160256
#define SM_FLAG  (SM_IDX + 512)               // 160768
#define SM_NFL   (SM_FLAG + 512)              // 161280
#define SM_TOTAL (SM_NFL + 16)                // 161296

// ---------------- device globals ----------------
__device__ double        g_loss[LAYERS];
__device__ unsigned int  g_counts[LAYERS * KCODES];
__device__ float         g_esq[LAYERS * KCODES];
__device__ unsigned int  g_cmaxb[LAYERS];    // max ||c_k|| per layer (float bits)
__device__ unsigned int  g_clomaxb[LAYERS];  // max ||c_k - bf16(c_k)|| per layer
__device__ __nv_bfloat16 g_cbh[LAYERS * KCODES * DIM];
__device__ float         g_resid[(size_t)N_TOK * DIM];   // EXACT fp32 residual chain

// ---------------- helpers ----------------
__device__ __forceinline__ uint32_t smem_u32p(const void* p) {
    uint32_t a;
    asm("{ .reg .u64 t; cvta.to.shared.u64 t, %1; cvt.u32.u64 %0, t; }" : "=r"(a) : "l"(p));
    return a;
}
__device__ __forceinline__ float ulo(uint32_t u) { return __uint_as_float(u << 16); }
__device__ __forceinline__ uint32_t b2u(float v) {
    return (uint32_t)__bfloat16_as_ushort(__float2bfloat16(v));
}
// hi bf16 pair (packed) + fp32 remainders
__device__ __forceinline__ uint32_t splithi(float v0, float v1, float& r0, float& r1) {
    uint32_t h0 = b2u(v0), h1 = b2u(v1);
    r0 = v0 - ulo(h0); r1 = v1 - ulo(h1);
    return h0 | (h1 << 16);
}

__device__ __forceinline__ void ldsm_x4(uint32_t* r, uint32_t addr) {
    asm volatile("ldmatrix.sync.aligned.m8n8.x4.shared.b16 {%0,%1,%2,%3}, [%4];"
        : "=r"(r[0]), "=r"(r[1]), "=r"(r[2]), "=r"(r[3]) : "r"(addr));
}
__device__ __forceinline__ void mma16816(float* c, const uint32_t* a, uint32_t b0, uint32_t b1) {
    asm volatile("mma.sync.aligned.m16n8k16.row.col.f32.bf16.bf16.f32 "
        "{%0,%1,%2,%3}, {%4,%5,%6,%7}, {%8,%9}, {%0,%1,%2,%3};"
        : "+f"(c[0]), "+f"(c[1]), "+f"(c[2]), "+f"(c[3])
        : "r"(a[0]), "r"(a[1]), "r"(a[2]), "r"(a[3]), "r"(b0), "r"(b1));
}
#define CP16(dst, src) asm volatile("cp.async.cg.shared.global [%0], [%1], 16;" :: "r"(dst), "l"(src))
#define CP_COMMIT()    asm volatile("cp.async.commit_group;" ::: "memory")
#define CP_WAIT2()     asm volatile("cp.async.wait_group 2;" ::: "memory")

// sorted top-4 insert (strict < ; exact rescore re-arbitrates, set semantics only)
__device__ __forceinline__ void top4_ins(float v, int c, float* cv, int* ci) {
    if (v < cv[3]) {
        if (v < cv[2]) {
            cv[3] = cv[2]; ci[3] = ci[2];
            if (v < cv[1]) {
                cv[2] = cv[1]; ci[2] = ci[1];
                if (v < cv[0]) { cv[1] = cv[0]; ci[1] = ci[0]; cv[0] = v; ci[0] = c; }
                else           { cv[1] = v; ci[1] = c; }
            } else { cv[2] = v; ci[2] = c; }
        } else { cv[3] = v; ci[3] = c; }
    }
}

// ---------------- prep kernels ----------------
__global__ void rvq_init_kernel() {
    int t = blockIdx.x * blockDim.x + threadIdx.x;
    if (t < LAYERS) { g_loss[t] = 0.0; g_cmaxb[t] = 0u; g_clomaxb[t] = 0u; }
    for (int i = t; i < LAYERS * KCODES; i += blockDim.x * gridDim.x) g_counts[i] = 0u;
}

// one warp per codebook row: hi split + esq + per-layer norm maxima
__global__ void rvq_prep_kernel(const float* __restrict__ cb) {
    int w = (blockIdx.x * blockDim.x + threadIdx.x) >> 5;
    int lane = threadIdx.x & 31;
    if (w >= LAYERS * KCODES) return;
    const float* row = cb + (size_t)w * DIM;
    __nv_bfloat16* ph = g_cbh + (size_t)w * DIM;
    double s = 0.0;
    float slo = 0.f;
    #pragma unroll
    for (int j = 0; j < 8; j++) {
        int d = lane + 32 * j;
        float v = row[d];
        s += (double)v * (double)v;
        __nv_bfloat16 hb = __float2bfloat16(v);
        ph[d] = hb;
        float lo = v - __bfloat162float(hb);
        slo += lo * lo;
    }
    #pragma unroll
    for (int off = 16; off; off >>= 1) {
        s   += __shfl_down_sync(0xffffffffu, s, off);
        slo += __shfl_down_sync(0xffffffffu, slo, off);
    }
    if (lane == 0) {
        g_esq[w] = (float)s;
        atomicMax(&g_cmaxb[w >> 10],   __float_as_uint(sqrtf((float)s)));
        atomicMax(&g_clomaxb[w >> 10], __float_as_uint(sqrtf(slo)));
    }
}

// ---------------- main kernel ----------------
extern __shared__ char smc[];

__global__ __launch_bounds__(THREADS, 1)
void rvq_main_kernel(const float* __restrict__ z,
                     const float* __restrict__ codebooks,
                     float* __restrict__ out)
{
    const int tid  = threadIdx.x;
    const int lane = tid & 31;
    const int wid  = tid >> 5;
    const int wm   = wid & 3;
    const int wn   = wid >> 2;
    const int m0   = blockIdx.x * 128;

    const uint32_t sb = smem_u32p(smc);
    uint32_t* AhU = (uint32_t*)(smc + SM_AH);
    float*  sE    = (float*)(smc + SM_SE);
    float*  sZsq  = (float*)(smc + SM_ZSQ);
    float*  sPart = (float*)(smc + SM_PART);
    float*  sPart2= (float*)(smc + SM_PART2);
    float*  sMar  = (float*)(smc + SM_MAR);
    float*  sGmin = (float*)(smc + SM_GMIN);
    float*  sGm2  = (float*)(smc + SM_GM2);
    int*    sCCnt = (int*)(smc + SM_CCNT);
    int*    sFull = (int*)(smc + SM_FULL);
    unsigned short* sCand = (unsigned short*)(smc + SM_CAND);
    unsigned long long* sBest = (unsigned long long*)(smc + SM_BEST);
    int*    sIdx  = (int*)(smc + SM_IDX);
    int*    sFlag = (int*)(smc + SM_FLAG);
    int*    sNFl  = (int*)(smc + SM_NFL);

    const int g  = lane >> 3, lr = lane & 7;
    const int rofs = lr + (g & 1) * 8;
    const int kofs = (g >> 1) * 8;
    const uint32_t aA_base = sb + SM_AH + (uint32_t)(wm * 32 + rofs) * AROW + kofs * 2;
    const uint32_t aB_lane = (uint32_t)(wn * 64 + rofs) * BROW + kofs * 2;

    auto produce = [&](int t) {
        int pl8 = t >> 5, pnc = (t >> 2) & 7, pdc = t & 3;
        const __nv_bfloat16* src0 = g_cbh + ((size_t)(pl8 * KCODES + pnc * 128) * DIM) + pdc * 64;
        uint32_t dst0 = sb + SM_B + (uint32_t)(t & 3) * BSTAGE;
        #pragma unroll
        for (int i = 0; i < 4; i++) {
            int id = tid + 256 * i;
            int row = id >> 3, c = id & 7;
            CP16(dst0 + (uint32_t)row * BROW + c * 16, src0 + (size_t)row * DIM + c * 8);
        }
    };

    produce(0); CP_COMMIT();
    produce(1); CP_COMMIT();
    produce(2); CP_COMMIT();

    // split z (hi into smem A), exact zsq + lo-norm partials
    {
        int mtk = tid >> 1, hb = tid & 1;
        const float4* zrow = (const float4*)(z + (size_t)(m0 + mtk) * DIM + hb * 128);
        float zs = 0.f, l2 = 0.f;
        #pragma unroll 8
        for (int j4 = 0; j4 < 32; j4++) {
            float4 v = zrow[j4];
            zs = fmaf(v.x, v.x, zs); zs = fmaf(v.y, v.y, zs);
            zs = fmaf(v.z, v.z, zs); zs = fmaf(v.w, v.w, zs);
            float e0, e1, e2, e3;
            uint32_t h0 = splithi(v.x, v.y, e0, e1);
            uint32_t h1 = splithi(v.z, v.w, e2, e3);
            l2 += e0 * e0 + e1 * e1 + e2 * e2 + e3 * e3;
            uint32_t pa = (uint32_t)mtk * AROWU + hb * 64 + j4 * 2;
            AhU[pa] = h0; AhU[pa + 1] = h1;
        }
        sPart[tid] = zs; sPart2[tid] = l2;
    }
    for (int i = tid; i < KCODES; i += THREADS) sE[i] = g_esq[i];
    __syncthreads();
    if (tid < 128) {
        float zs = sPart[2 * tid] + sPart[2 * tid + 1];
        float la = sqrtf(sPart2[2 * tid] + sPart2[2 * tid + 1]);
        sZsq[tid] = zs;
        float cm = __uint_as_float(g_cmaxb[0]);
        float cl = __uint_as_float(g_clomaxb[0]);
        sMar[tid] = 4.0f * (la * cm + (sqrtf(zs) + la) * cl) + 5e-3f;
    }
    __syncthreads();

    int tcur = 0;
    for (int lay = 0; lay < LAYERS; lay++) {
        const float* rl = (lay == 0) ? z : g_resid;

        if (tid < 128) { sCCnt[tid] = 0; sFull[tid] = 0; sBest[tid] = ~0ull; }
        if (tid == 0) *sNFl = 0;

        float zq[4];
        #pragma unroll
        for (int s = 0; s < 4; s++)
            zq[s] = sZsq[wm * 32 + (s >> 1) * 16 + (s & 1) * 8 + (lane >> 2)];
        float cv[4][4]; int ci[4][4];
        #pragma unroll
        for (int s = 0; s < 4; s++)
            #pragma unroll
            for (int j = 0; j < 4; j++) { cv[s][j] = 3.4e38f; ci[s][j] = 0; }

        for (int nc = 0; nc < 8; nc++) {
            float acc[2][8][4];
            #pragma unroll
            for (int ma = 0; ma < 2; ma++)
                #pragma unroll
                for (int na = 0; na < 8; na++)
                    #pragma unroll
                    for (int v = 0; v < 4; v++) acc[ma][na][v] = 0.f;

            for (int dc = 0; dc < 4; dc++) {
                CP_WAIT2();
                __syncthreads();
                if (tcur + 3 < NT_TILES) { produce(tcur + 3); CP_COMMIT(); }
                uint32_t bst = sb + SM_B + (uint32_t)(tcur & 3) * BSTAGE;
                #pragma unroll
                for (int ks = 0; ks < 4; ks++) {
                    int k0 = ks * 16, kA = dc * 64 + k0;
                    uint32_t bf[16];
                    #pragma unroll
                    for (int np = 0; np < 4; np++)
                        ldsm_x4(bf + np * 4, bst + aB_lane + (uint32_t)(np * 16) * BROW + k0 * 2);
                    uint32_t af[4];
                    #pragma unroll
                    for (int ma = 0; ma < 2; ma++) {
                        ldsm_x4(af, aA_base + (uint32_t)(ma * 16) * AROW + kA * 2);
                        #pragma unroll
                        for (int na = 0; na < 8; na++) {
                            int np = na >> 1, o = na & 1;
                            mma16816(acc[ma][na], af, bf[np * 4 + o], bf[np * 4 + o + 2]);
                        }
                    }
                }
                tcur++;
            }

            // epilogue: approx distances -> per-slot top-4
            #pragma unroll
            for (int na = 0; na < 8; na++) {
                int cbase = nc * 128 + wn * 64 + na * 8 + (lane & 3) * 2;
                float2 e = *(float2*)&sE[cbase];
                #pragma unroll
                for (int ma = 0; ma < 2; ma++) {
                    float* d = acc[ma][na];
                    int s0 = ma * 2, s1 = ma * 2 + 1;
                    float v0 = fmaf(-2.0f, d[0], zq[s0] + e.x);
                    float v1 = fmaf(-2.0f, d[1], zq[s0] + e.y);
                    top4_ins(v0, cbase,     cv[s0], ci[s0]);
                    top4_ins(v1, cbase + 1, cv[s0], ci[s0]);
                    float w0 = fmaf(-2.0f, d[2], zq[s1] + e.x);
                    float w1 = fmaf(-2.0f, d[3], zq[s1] + e.y);
                    top4_ins(w0, cbase,     cv[s1], ci[s1]);
                    top4_ins(w1, cbase + 1, cv[s1], ci[s1]);
                }
            }
        }

        // global approx min per token
        float gm[4] = {cv[0][0], cv[1][0], cv[2][0], cv[3][0]};
        #pragma unroll
        for (int off = 1; off <= 2; off <<= 1)
            #pragma unroll
            for (int s = 0; s < 4; s++)
                gm[s] = fminf(gm[s], __shfl_xor_sync(0xffffffffu, gm[s], off));
        if ((lane & 3) == 0) {
            #pragma unroll
            for (int s = 0; s < 4; s++) {
                int row = wm * 32 + (s >> 1) * 16 + (s & 1) * 8 + (lane >> 2);
                sGm2[row * 2 + wn] = gm[s];
            }
        }
        __syncthreads();
        if (tid < 128) sGmin[tid] = fminf(sGm2[2 * tid], sGm2[2 * tid + 1]);
        __syncthreads();

        // candidate filter (rigorous margin) + completeness check
        #pragma unroll
        for (int s = 0; s < 4; s++) {
            int row = wm * 32 + (s >> 1) * 16 + (s & 1) * 8 + (lane >> 2);
            float thr = sGmin[row] + sMar[row];
            if (cv[s][3] <= thr) sFull[row] = 1;
            #pragma unroll
            for (int j = 0; j < 4; j++) {
                if (cv[s][j] <= thr) {
                    int pos = atomicAdd(&sCCnt[row], 1);
                    sCand[row * 32 + pos] = (unsigned short)ci[s][j];
                }
            }
        }
        __syncthreads();
        if (tid < 128 && sFull[tid]) { int p = atomicAdd(sNFl, 1); sFlag[p] = tid; }
        __syncthreads();

        // exact fp32 scoring of candidates (serial ascending fma; exact residual)
        {
            int tok = tid >> 1, sub = tid & 1;
            if (!sFull[tok]) {
                int cnt = sCCnt[tok];
                float zqs = sZsq[tok];
                const float4* rrow4 = (const float4*)(rl + (size_t)(m0 + tok) * DIM);
                for (int j = sub; j < cnt; j += 2) {
                    int c = sCand[tok * 32 + j];
                    const float4* crow = (const float4*)(codebooks +
                        ((size_t)lay * KCODES + c) * DIM);
                    float dot = 0.f;
                    #pragma unroll 8
                    for (int q4 = 0; q4 < 64; q4++) {
                        float4 cvv = crow[q4]; float4 rv = rrow4[q4];
                        dot = fmaf(rv.x, cvv.x, dot); dot = fmaf(rv.y, cvv.y, dot);
                        dot = fmaf(rv.z, cvv.z, dot); dot = fmaf(rv.w, cvv.w, dot);
                    }
                    float dist = fmaf(-2.0f, dot, zqs + sE[c]);
                    unsigned long long pk =
                        ((unsigned long long)__float_as_uint(dist) << 32) | (unsigned)c;
                    atomicMin(&sBest[tok], pk);
                }
            }
        }
        // rare fallback: full 1024-code exact rescan
        {
            int nf = *sNFl;
            for (int f = 0; f < nf; f++) {
                int tok = sFlag[f];
                float zqs = sZsq[tok];
                const float4* rrow4 = (const float4*)(rl + (size_t)(m0 + tok) * DIM);
                #pragma unroll
                for (int j = 0; j < 4; j++) {
                    int c = tid + 256 * j;
                    const float4* crow = (const float4*)(codebooks +
                        ((size_t)lay * KCODES + c) * DIM);
                    float dot = 0.f;
                    #pragma unroll 8
                    for (int q4 = 0; q4 < 64; q4++) {
                        float4 cvv = crow[q4]; float4 rv = rrow4[q4];
                        dot = fmaf(rv.x, cvv.x, dot); dot = fmaf(rv.y, cvv.y, dot);
                        dot = fmaf(rv.z, cvv.z, dot); dot = fmaf(rv.w, cvv.w, dot);
                    }
                    float dist = fmaf(-2.0f, dot, zqs + sE[c]);
                    unsigned long long pk =
                        ((unsigned long long)__float_as_uint(dist) << 32) | (unsigned)c;
                    atomicMin(&sBest[tok], pk);
                }
            }
        }
        __syncthreads();

        if (tid < 128) {
            int idx = (int)(sBest[tid] & 0xFFFFFFFFull);
            sIdx[tid] = idx;
            out[(size_t)N_TOK * DIM + (size_t)lay * N_TOK + m0 + tid] = (float)idx;
            atomicAdd(&g_counts[lay * KCODES + idx], 1u);
        }
        __syncthreads();

        // update from EXACT residual; write exact chain + fresh hi split
        {
            int mtk = tid >> 1, hb = tid & 1;
            int idx = sIdx[mtk];
            size_t tok = (size_t)(m0 + mtk);
            const float4* crow = (const float4*)(codebooks +
                ((size_t)lay * KCODES + idx) * DIM + hb * 128);
            const float4* rrow = (const float4*)(rl + tok * DIM + hb * 128);
            float4* wrow = (float4*)(g_resid + tok * DIM + hb * 128);
            const float4* zrow = (const float4*)(z + tok * DIM + hb * 128);
            float4* orow = (float4*)(out + tok * DIM + hb * 128);
            float lss = 0.f, zs = 0.f, l2 = 0.f;
            #pragma unroll 4
            for (int j4 = 0; j4 < 32; j4++) {
                float4 q = crow[j4];
                float4 r = rrow[j4];
                float d0 = r.x - q.x, d1 = r.y - q.y, d2 = r.z - q.z, d3 = r.w - q.w;
                lss = fmaf(d0, d0, lss); lss = fmaf(d1, d1, lss);
                lss = fmaf(d2, d2, lss); lss = fmaf(d3, d3, lss);
                float n0 = r.x - (r.x + (q.x - r.x));
                float n1 = r.y - (r.y + (q.y - r.y));
                float n2 = r.z - (r.z + (q.z - r.z));
                float n3 = r.w - (r.w + (q.w - r.w));
                if (lay < 7) {
                    zs = fmaf(n0, n0, zs); zs = fmaf(n1, n1, zs);
                    zs = fmaf(n2, n2, zs); zs = fmaf(n3, n3, zs);
                    float4 nw; nw.x = n0; nw.y = n1; nw.z = n2; nw.w = n3;
                    wrow[j4] = nw;
                    float e0, e1, e2, e3;
                    uint32_t h0 = splithi(n0, n1, e0, e1);
                    uint32_t h1 = splithi(n2, n3, e2, e3);
                    l2 += e0 * e0 + e1 * e1 + e2 * e2 + e3 * e3;
                    uint32_t pa = (uint32_t)mtk * AROWU + hb * 64 + j4 * 2;
                    AhU[pa] = h0; AhU[pa + 1] = h1;
                } else {
                    float4 zv = zrow[j4];
                    float4 ov;
                    ov.x = zv.x - n0; ov.y = zv.y - n1; ov.z = zv.z - n2; ov.w = zv.w - n3;
                    orow[j4] = ov;
                }
            }
            sPart[tid] = zs; sPart2[tid] = l2;
            #pragma unroll
            for (int off = 16; off; off >>= 1)
                lss += __shfl_down_sync(0xffffffffu, lss, off);
            if (lane == 0) atomicAdd(&g_loss[lay], (double)lss);
        }
        __syncthreads();
        if (lay < 7) {
            if (tid < 128) {
                float zs = sPart[2 * tid] + sPart[2 * tid + 1];
                float la = sqrtf(sPart2[2 * tid] + sPart2[2 * tid + 1]);
                sZsq[tid] = zs;
                float cm = __uint_as_float(g_cmaxb[lay + 1]);
                float cl = __uint_as_float(g_clomaxb[lay + 1]);
                sMar[tid] = 4.0f * (la * cm + (sqrtf(zs) + la) * cl) + 5e-3f;
            }
            for (int i = tid; i < KCODES; i += THREADS) sE[i] = g_esq[(lay + 1) * KCODES + i];
            __syncthreads();
        }
    }
}

// ---------------- finalize ----------------
__global__ void rvq_final_kernel(float* __restrict__ out) {
    __shared__ double red[8];
    int t = threadIdx.x;
    double total_perp = 0.0;
    for (int l = 0; l < LAYERS; l++) {
        double local = 0.0;
        for (int k = t; k < KCODES; k += 256) {
            float p = (float)g_counts[l * KCODES + k] / (float)N_TOK;
            local += (double)(p * logf(p + 1e-10f));
        }
        #pragma unroll
        for (int off = 16; off; off >>= 1)
            local += __shfl_down_sync(0xffffffffu, local, off);
        if ((t & 31) == 0) red[t >> 5] = local;
        __syncthreads();
        if (t == 0) {
            double s = 0.0;
            for (int w = 0; w < 8; w++) s += red[w];
            total_perp += exp(-s);
        }
        __syncthreads();
    }
    if (t == 0) {
        double tc = 0.0;
        for (int l = 0; l < LAYERS; l++)
            tc += g_loss[l] / ((double)N_TOK * (double)DIM);
        size_t off = (size_t)N_TOK * DIM + (size_t)LAYERS * N_TOK;
        out[off + 0] = (float)(0.25 * tc + tc);
        out[off + 1] = (float)tc;
        out[off + 2] = (float)tc;
        out[off + 3] = (float)(total_perp / (double)LAYERS);
    }
}

// ---------------- launch ----------------
extern "C" void kernel_launch(void* const* d_in, const int* in_sizes, int n_in,
                              void* d_out, int out_size) {
    const float* z  = (const float*)d_in[0];
    const float* cb = (const float*)d_in[1];
    float* out = (float*)d_out;

    cudaFuncSetAttribute(rvq_main_kernel,
                         cudaFuncAttributeMaxDynamicSharedMemorySize, SM_TOTAL);

    rvq_init_kernel<<<1, 256>>>();
    rvq_prep_kernel<<<(LAYERS * KCODES * 32 + 255) / 256, 256>>>(cb);
    rvq_main_kernel<<<N_TOK / 128, THREADS, SM_TOTAL>>>(z, cb, out);
    rvq_final_kernel<<<1, 256>>>(out);
}

// round 10
// speedup vs baseline: 2.9221x; 1.2139x over previous
#include <cuda_runtime.h>
#include <cuda_bf16.h>
#include <math.h>
#include <stdint.h>

#define N_TOK   65536
#define DIM     256
#define KCODES  1024
#define LAYERS  8
#define THREADS 256
#define TOKB    64            // tokens per CTA
#define NT_TILES 256          // 8 layers * 8 nchunks * 4 dchunks (hi split only)
#define BROW    144           // B smem row bytes: 64 dims*2B + 16B pad
#define BSTAGE  (128*BROW)    // 18432 B per stage
#define NSTAGE  3
#define AROW    528           // A smem row bytes: 264 bf16 (256 + 8 pad)
#define AROWU   132           // A row stride in u32

// smem byte offsets
#define SM_AH    0
#define SM_B     (SM_AH + TOKB*AROW)          // 33792
#define SM_SE    (SM_B + NSTAGE*BSTAGE)       // 89088
#define SM_ZSQ   (SM_SE + 4096)               // 93184
#define SM_PART  (SM_ZSQ + 256)               // 93440
#define SM_PART2 (SM_PART + 1024)             // 94464
#define SM_MAR   (SM_PART2 + 1024)            // 95488
#define SM_GMIN  (SM_MAR + 256)               // 95744
#define SM_GM2   (SM_GMIN + 256)              // 96000  f32[64][4]
#define SM_CCNT  (SM_GM2 + 1024)              // 97024
#define SM_FULL  (SM_CCNT + 256)              // 97280
#define SM_CAND  (SM_FULL + 256)              // 97536  u16[64][64]
#define SM_BEST  (SM_CAND + 8192)             // 105728 u64[64]
#define SM_IDX   (SM_BEST + 512)              // 106240
#define SM_FLAG  (SM_IDX + 256)               // 106496
#define SM_NFL   (SM_FLAG + 256)              // 106752
#define SM_TOTAL (SM_NFL + 16)                // 106768

// ---------------- device globals ----------------
__device__ double        g_loss[LAYERS];
__device__ unsigned int  g_counts[LAYERS * KCODES];
__device__ float         g_esq[LAYERS * KCODES];
__device__ unsigned int  g_cmaxb[LAYERS];
__device__ unsigned int  g_clomaxb[LAYERS];
__device__ __nv_bfloat16 g_cbh[LAYERS * KCODES * DIM];
__device__ float         g_resid[(size_t)N_TOK * DIM];   // EXACT fp32 residual chain

// ---------------- helpers ----------------
__device__ __forceinline__ uint32_t smem_u32p(const void* p) {
    uint32_t a;
    asm("{ .reg .u64 t; cvta.to.shared.u64 t, %1; cvt.u32.u64 %0, t; }" : "=r"(a) : "l"(p));
    return a;
}
__device__ __forceinline__ float ulo(uint32_t u) { return __uint_as_float(u << 16); }
__device__ __forceinline__ uint32_t b2u(float v) {
    return (uint32_t)__bfloat16_as_ushort(__float2bfloat16(v));
}
__device__ __forceinline__ uint32_t splithi(float v0, float v1, float& r0, float& r1) {
    uint32_t h0 = b2u(v0), h1 = b2u(v1);
    r0 = v0 - ulo(h0); r1 = v1 - ulo(h1);
    return h0 | (h1 << 16);
}

__device__ __forceinline__ void ldsm_x4(uint32_t* r, uint32_t addr) {
    asm volatile("ldmatrix.sync.aligned.m8n8.x4.shared.b16 {%0,%1,%2,%3}, [%4];"
        : "=r"(r[0]), "=r"(r[1]), "=r"(r[2]), "=r"(r[3]) : "r"(addr));
}
__device__ __forceinline__ void mma16816(float* c, const uint32_t* a, uint32_t b0, uint32_t b1) {
    asm volatile("mma.sync.aligned.m16n8k16.row.col.f32.bf16.bf16.f32 "
        "{%0,%1,%2,%3}, {%4,%5,%6,%7}, {%8,%9}, {%0,%1,%2,%3};"
        : "+f"(c[0]), "+f"(c[1]), "+f"(c[2]), "+f"(c[3])
        : "r"(a[0]), "r"(a[1]), "r"(a[2]), "r"(a[3]), "r"(b0), "r"(b1));
}
#define CP16(dst, src) asm volatile("cp.async.cg.shared.global [%0], [%1], 16;" :: "r"(dst), "l"(src))
#define CP_COMMIT()    asm volatile("cp.async.commit_group;" ::: "memory")
#define CP_WAIT1()     asm volatile("cp.async.wait_group 1;" ::: "memory")

__device__ __forceinline__ void top4_ins(float v, int c, float* cv, int* ci) {
    if (v < cv[3]) {
        if (v < cv[2]) {
            cv[3] = cv[2]; ci[3] = ci[2];
            if (v < cv[1]) {
                cv[2] = cv[1]; ci[2] = ci[1];
                if (v < cv[0]) { cv[1] = cv[0]; ci[1] = ci[0]; cv[0] = v; ci[0] = c; }
                else           { cv[1] = v; ci[1] = c; }
            } else { cv[2] = v; ci[2] = c; }
        } else { cv[3] = v; ci[3] = c; }
    }
}

// ---------------- prep kernels ----------------
__global__ void rvq_init_kernel() {
    int t = blockIdx.x * blockDim.x + threadIdx.x;
    if (t < LAYERS) { g_loss[t] = 0.0; g_cmaxb[t] = 0u; g_clomaxb[t] = 0u; }
    for (int i = t; i < LAYERS * KCODES; i += blockDim.x * gridDim.x) g_counts[i] = 0u;
}

__global__ void rvq_prep_kernel(const float* __restrict__ cb) {
    int w = (blockIdx.x * blockDim.x + threadIdx.x) >> 5;
    int lane = threadIdx.x & 31;
    if (w >= LAYERS * KCODES) return;
    const float* row = cb + (size_t)w * DIM;
    __nv_bfloat16* ph = g_cbh + (size_t)w * DIM;
    double s = 0.0;
    float slo = 0.f;
    #pragma unroll
    for (int j = 0; j < 8; j++) {
        int d = lane + 32 * j;
        float v = row[d];
        s += (double)v * (double)v;
        __nv_bfloat16 hb = __float2bfloat16(v);
        ph[d] = hb;
        float lo = v - __bfloat162float(hb);
        slo += lo * lo;
    }
    #pragma unroll
    for (int off = 16; off; off >>= 1) {
        s   += __shfl_down_sync(0xffffffffu, s, off);
        slo += __shfl_down_sync(0xffffffffu, slo, off);
    }
    if (lane == 0) {
        g_esq[w] = (float)s;
        atomicMax(&g_cmaxb[w >> 10],   __float_as_uint(sqrtf((float)s)));
        atomicMax(&g_clomaxb[w >> 10], __float_as_uint(sqrtf(slo)));
    }
}

// ---------------- main kernel ----------------
extern __shared__ char smc[];

__global__ __launch_bounds__(THREADS, 2)
void rvq_main_kernel(const float* __restrict__ z,
                     const float* __restrict__ codebooks,
                     float* __restrict__ out)
{
    const int tid  = threadIdx.x;
    const int lane = tid & 31;
    const int wid  = tid >> 5;
    const int wm   = wid & 1;        // 2 warp rows (32 tokens each)
    const int wn   = wid >> 1;       // 4 warp cols (32 codes each)
    const int m0   = blockIdx.x * TOKB;

    const uint32_t sb = smem_u32p(smc);
    uint32_t* AhU = (uint32_t*)(smc + SM_AH);
    float*  sE    = (float*)(smc + SM_SE);
    float*  sZsq  = (float*)(smc + SM_ZSQ);
    float*  sPart = (float*)(smc + SM_PART);
    float*  sPart2= (float*)(smc + SM_PART2);
    float*  sMar  = (float*)(smc + SM_MAR);
    float*  sGmin = (float*)(smc + SM_GMIN);
    float*  sGm2  = (float*)(smc + SM_GM2);
    int*    sCCnt = (int*)(smc + SM_CCNT);
    int*    sFull = (int*)(smc + SM_FULL);
    unsigned short* sCand = (unsigned short*)(smc + SM_CAND);
    unsigned long long* sBest = (unsigned long long*)(smc + SM_BEST);
    int*    sIdx  = (int*)(smc + SM_IDX);
    int*    sFlag = (int*)(smc + SM_FLAG);
    int*    sNFl  = (int*)(smc + SM_NFL);

    const int g  = lane >> 3, lr = lane & 7;
    const int rofs = lr + (g & 1) * 8;
    const int kofs = (g >> 1) * 8;
    const uint32_t aA_base = sb + SM_AH + (uint32_t)(wm * 32 + rofs) * AROW + kofs * 2;
    const uint32_t aB_lane = (uint32_t)(wn * 32 + rofs) * BROW + kofs * 2;

    auto produce = [&](int t) {
        int pl8 = t >> 5, pnc = (t >> 2) & 7, pdc = t & 3;
        const __nv_bfloat16* src0 = g_cbh + ((size_t)(pl8 * KCODES + pnc * 128) * DIM) + pdc * 64;
        uint32_t dst0 = sb + SM_B + (uint32_t)(t % NSTAGE) * BSTAGE;
        #pragma unroll
        for (int i = 0; i < 4; i++) {
            int id = tid + 256 * i;
            int row = id >> 3, c = id & 7;
            CP16(dst0 + (uint32_t)row * BROW + c * 16, src0 + (size_t)row * DIM + c * 8);
        }
    };

    produce(0); CP_COMMIT();
    produce(1); CP_COMMIT();

    // split z (hi into smem A), exact zsq + lo-norm partials (4 threads/token)
    {
        int mtk = tid >> 2, hb = tid & 3;
        const float4* zrow = (const float4*)(z + (size_t)(m0 + mtk) * DIM + hb * 64);
        float zs = 0.f, l2 = 0.f;
        #pragma unroll 8
        for (int j4 = 0; j4 < 16; j4++) {
            float4 v = zrow[j4];
            zs = fmaf(v.x, v.x, zs); zs = fmaf(v.y, v.y, zs);
            zs = fmaf(v.z, v.z, zs); zs = fmaf(v.w, v.w, zs);
            float e0, e1, e2, e3;
            uint32_t h0 = splithi(v.x, v.y, e0, e1);
            uint32_t h1 = splithi(v.z, v.w, e2, e3);
            l2 += e0 * e0 + e1 * e1 + e2 * e2 + e3 * e3;
            uint32_t pa = (uint32_t)mtk * AROWU + hb * 32 + j4 * 2;
            AhU[pa] = h0; AhU[pa + 1] = h1;
        }
        sPart[tid] = zs; sPart2[tid] = l2;
    }
    for (int i = tid; i < KCODES; i += THREADS) sE[i] = g_esq[i];
    __syncthreads();
    if (tid < TOKB) {
        float zs = (sPart[4 * tid] + sPart[4 * tid + 1]) + (sPart[4 * tid + 2] + sPart[4 * tid + 3]);
        float l2 = (sPart2[4 * tid] + sPart2[4 * tid + 1]) + (sPart2[4 * tid + 2] + sPart2[4 * tid + 3]);
        float la = sqrtf(l2);
        sZsq[tid] = zs;
        float cm = __uint_as_float(g_cmaxb[0]);
        float cl = __uint_as_float(g_clomaxb[0]);
        sMar[tid] = 4.0f * (la * cm + (sqrtf(zs) + la) * cl) + 5e-3f;
    }
    __syncthreads();

    int tcur = 0;
    for (int lay = 0; lay < LAYERS; lay++) {
        const float* rl = (lay == 0) ? z : g_resid;

        if (tid < TOKB) { sCCnt[tid] = 0; sFull[tid] = 0; sBest[tid] = ~0ull; }
        if (tid == 0) *sNFl = 0;

        float zq[4];
        #pragma unroll
        for (int s = 0; s < 4; s++)
            zq[s] = sZsq[wm * 32 + (s >> 1) * 16 + (s & 1) * 8 + (lane >> 2)];
        float cv[4][4]; int ci[4][4];
        #pragma unroll
        for (int s = 0; s < 4; s++)
            #pragma unroll
            for (int j = 0; j < 4; j++) { cv[s][j] = 3.4e38f; ci[s][j] = 0; }

        for (int nc = 0; nc < 8; nc++) {
            float acc[2][4][4];
            #pragma unroll
            for (int ma = 0; ma < 2; ma++)
                #pragma unroll
                for (int na = 0; na < 4; na++)
                    #pragma unroll
                    for (int v = 0; v < 4; v++) acc[ma][na][v] = 0.f;

            for (int dc = 0; dc < 4; dc++) {
                CP_WAIT1();
                __syncthreads();
                if (tcur + 2 < NT_TILES) { produce(tcur + 2); CP_COMMIT(); }
                uint32_t bst = sb + SM_B + (uint32_t)(tcur % NSTAGE) * BSTAGE;
                #pragma unroll
                for (int ks = 0; ks < 4; ks++) {
                    int k0 = ks * 16, kA = dc * 64 + k0;
                    uint32_t bf[8];
                    #pragma unroll
                    for (int np = 0; np < 2; np++)
                        ldsm_x4(bf + np * 4, bst + aB_lane + (uint32_t)(np * 16) * BROW + k0 * 2);
                    uint32_t af[4];
                    #pragma unroll
                    for (int ma = 0; ma < 2; ma++) {
                        ldsm_x4(af, aA_base + (uint32_t)(ma * 16) * AROW + kA * 2);
                        #pragma unroll
                        for (int na = 0; na < 4; na++) {
                            int np = na >> 1, o = na & 1;
                            mma16816(acc[ma][na], af, bf[np * 4 + o], bf[np * 4 + o + 2]);
                        }
                    }
                }
                tcur++;
            }

            // epilogue: approx distances -> per-slot top-4
            #pragma unroll
            for (int na = 0; na < 4; na++) {
                int cbase = nc * 128 + wn * 32 + na * 8 + (lane & 3) * 2;
                float2 e = *(float2*)&sE[cbase];
                #pragma unroll
                for (int ma = 0; ma < 2; ma++) {
                    float* d = acc[ma][na];
                    int s0 = ma * 2, s1 = ma * 2 + 1;
                    float v0 = fmaf(-2.0f, d[0], zq[s0] + e.x);
                    float v1 = fmaf(-2.0f, d[1], zq[s0] + e.y);
                    top4_ins(v0, cbase,     cv[s0], ci[s0]);
                    top4_ins(v1, cbase + 1, cv[s0], ci[s0]);
                    float w0 = fmaf(-2.0f, d[2], zq[s1] + e.x);
                    float w1 = fmaf(-2.0f, d[3], zq[s1] + e.y);
                    top4_ins(w0, cbase,     cv[s1], ci[s1]);
                    top4_ins(w1, cbase + 1, cv[s1], ci[s1]);
                }
            }
        }

        // global approx min per token (4 lanes share a row, then 4 wn)
        float gm[4] = {cv[0][0], cv[1][0], cv[2][0], cv[3][0]};
        #pragma unroll
        for (int off = 1; off <= 2; off <<= 1)
            #pragma unroll
            for (int s = 0; s < 4; s++)
                gm[s] = fminf(gm[s], __shfl_xor_sync(0xffffffffu, gm[s], off));
        if ((lane & 3) == 0) {
            #pragma unroll
            for (int s = 0; s < 4; s++) {
                int row = wm * 32 + (s >> 1) * 16 + (s & 1) * 8 + (lane >> 2);
                sGm2[row * 4 + wn] = gm[s];
            }
        }
        __syncthreads();
        if (tid < TOKB)
            sGmin[tid] = fminf(fminf(sGm2[4 * tid], sGm2[4 * tid + 1]),
                               fminf(sGm2[4 * tid + 2], sGm2[4 * tid + 3]));
        __syncthreads();

        // candidate filter (rigorous margin) + completeness check
        #pragma unroll
        for (int s = 0; s < 4; s++) {
            int row = wm * 32 + (s >> 1) * 16 + (s & 1) * 8 + (lane >> 2);
            float thr = sGmin[row] + sMar[row];
            if (cv[s][3] <= thr) sFull[row] = 1;
            #pragma unroll
            for (int j = 0; j < 4; j++) {
                if (cv[s][j] <= thr) {
                    int pos = atomicAdd(&sCCnt[row], 1);
                    sCand[row * 64 + pos] = (unsigned short)ci[s][j];
                }
            }
        }
        __syncthreads();
        if (tid < TOKB && sFull[tid]) { int p = atomicAdd(sNFl, 1); sFlag[p] = tid; }
        __syncthreads();

        // exact fp32 scoring of candidates (serial ascending fma; exact residual)
        {
            int tok = tid >> 2, sub = tid & 3;
            if (!sFull[tok]) {
                int cnt = sCCnt[tok];
                float zqs = sZsq[tok];
                const float4* rrow4 = (const float4*)(rl + (size_t)(m0 + tok) * DIM);
                for (int j = sub; j < cnt; j += 4) {
                    int c = sCand[tok * 64 + j];
                    const float4* crow = (const float4*)(codebooks +
                        ((size_t)lay * KCODES + c) * DIM);
                    float dot = 0.f;
                    #pragma unroll 8
                    for (int q4 = 0; q4 < 64; q4++) {
                        float4 cvv = crow[q4]; float4 rv = rrow4[q4];
                        dot = fmaf(rv.x, cvv.x, dot); dot = fmaf(rv.y, cvv.y, dot);
                        dot = fmaf(rv.z, cvv.z, dot); dot = fmaf(rv.w, cvv.w, dot);
                    }
                    float dist = fmaf(-2.0f, dot, zqs + sE[c]);
                    unsigned long long pk =
                        ((unsigned long long)__float_as_uint(dist) << 32) | (unsigned)c;
                    atomicMin(&sBest[tok], pk);
                }
            }
        }
        // rare fallback: full 1024-code exact rescan
        {
            int nf = *sNFl;
            for (int f = 0; f < nf; f++) {
                int tok = sFlag[f];
                float zqs = sZsq[tok];
                const float4* rrow4 = (const float4*)(rl + (size_t)(m0 + tok) * DIM);
                #pragma unroll
                for (int j = 0; j < 4; j++) {
                    int c = tid + 256 * j;
                    const float4* crow = (const float4*)(codebooks +
                        ((size_t)lay * KCODES + c) * DIM);
                    float dot = 0.f;
                    #pragma unroll 8
                    for (int q4 = 0; q4 < 64; q4++) {
                        float4 cvv = crow[q4]; float4 rv = rrow4[q4];
                        dot = fmaf(rv.x, cvv.x, dot); dot = fmaf(rv.y, cvv.y, dot);
                        dot = fmaf(rv.z, cvv.z, dot); dot = fmaf(rv.w, cvv.w, dot);
                    }
                    float dist = fmaf(-2.0f, dot, zqs + sE[c]);
                    unsigned long long pk =
                        ((unsigned long long)__float_as_uint(dist) << 32) | (unsigned)c;
                    atomicMin(&sBest[tok], pk);
                }
            }
        }
        __syncthreads();

        if (tid < TOKB) {
            int idx = (int)(sBest[tid] & 0xFFFFFFFFull);
            sIdx[tid] = idx;
            out[(size_t)N_TOK * DIM + (size_t)lay * N_TOK + m0 + tid] = (float)idx;
            atomicAdd(&g_counts[lay * KCODES + idx], 1u);
        }
        __syncthreads();

        // update from EXACT residual; write exact chain + fresh hi split
        {
            int mtk = tid >> 2, hb = tid & 3;
            int idx = sIdx[mtk];
            size_t tok = (size_t)(m0 + mtk);
            const float4* crow = (const float4*)(codebooks +
                ((size_t)lay * KCODES + idx) * DIM + hb * 64);
            const float4* rrow = (const float4*)(rl + tok * DIM + hb * 64);
            float4* wrow = (float4*)(g_resid + tok * DIM + hb * 64);
            const float4* zrow = (const float4*)(z + tok * DIM + hb * 64);
            float4* orow = (float4*)(out + tok * DIM + hb * 64);
            float lss = 0.f, zs = 0.f, l2 = 0.f;
            #pragma unroll 4
            for (int j4 = 0; j4 < 16; j4++) {
                float4 q = crow[j4];
                float4 r = rrow[j4];
                float d0 = r.x - q.x, d1 = r.y - q.y, d2 = r.z - q.z, d3 = r.w - q.w;
                lss = fmaf(d0, d0, lss); lss = fmaf(d1, d1, lss);
                lss = fmaf(d2, d2, lss); lss = fmaf(d3, d3, lss);
                float n0 = r.x - (r.x + (q.x - r.x));
                float n1 = r.y - (r.y + (q.y - r.y));
                float n2 = r.z - (r.z + (q.z - r.z));
                float n3 = r.w - (r.w + (q.w - r.w));
                if (lay < 7) {
                    zs = fmaf(n0, n0, zs); zs = fmaf(n1, n1, zs);
                    zs = fmaf(n2, n2, zs); zs = fmaf(n3, n3, zs);
                    float4 nw; nw.x = n0; nw.y = n1; nw.z = n2; nw.w = n3;
                    wrow[j4] = nw;
                    float e0, e1, e2, e3;
                    uint32_t h0 = splithi(n0, n1, e0, e1);
                    uint32_t h1 = splithi(n2, n3, e2, e3);
                    l2 += e0 * e0 + e1 * e1 + e2 * e2 + e3 * e3;
                    uint32_t pa = (uint32_t)mtk * AROWU + hb * 32 + j4 * 2;
                    AhU[pa] = h0; AhU[pa + 1] = h1;
                } else {
                    float4 zv = zrow[j4];
                    float4 ov;
                    ov.x = zv.x - n0; ov.y = zv.y - n1; ov.z = zv.z - n2; ov.w = zv.w - n3;
                    orow[j4] = ov;
                }
            }
            sPart[tid] = zs; sPart2[tid] = l2;
            #pragma unroll
            for (int off = 16; off; off >>= 1)
                lss += __shfl_down_sync(0xffffffffu, lss, off);
            if (lane == 0) atomicAdd(&g_loss[lay], (double)lss);
        }
        __syncthreads();
        if (lay < 7) {
            if (tid < TOKB) {
                float zs = (sPart[4 * tid] + sPart[4 * tid + 1]) + (sPart[4 * tid + 2] + sPart[4 * tid + 3]);
                float l2 = (sPart2[4 * tid] + sPart2[4 * tid + 1]) + (sPart2[4 * tid + 2] + sPart2[4 * tid + 3]);
                float la = sqrtf(l2);
                sZsq[tid] = zs;
                float cm = __uint_as_float(g_cmaxb[lay + 1]);
                float cl = __uint_as_float(g_clomaxb[lay + 1]);
                sMar[tid] = 4.0f * (la * cm + (sqrtf(zs) + la) * cl) + 5e-3f;
            }
            for (int i = tid; i < KCODES; i += THREADS) sE[i] = g_esq[(lay + 1) * KCODES + i];
            __syncthreads();
        }
    }
}

// ---------------- finalize ----------------
__global__ void rvq_final_kernel(float* __restrict__ out) {
    __shared__ double red[8];
    int t = threadIdx.x;
    double total_perp = 0.0;
    for (int l = 0; l < LAYERS; l++) {
        double local = 0.0;
        for (int k = t; k < KCODES; k += 256) {
            float p = (float)g_counts[l * KCODES + k] / (float)N_TOK;
            local += (double)(p * logf(p + 1e-10f));
        }
        #pragma unroll
        for (int off = 16; off; off >>= 1)
            local += __shfl_down_sync(0xffffffffu, local, off);
        if ((t & 31) == 0) red[t >> 5] = local;
        __syncthreads();
        if (t == 0) {
            double s = 0.0;
            for (int w = 0; w < 8; w++) s += red[w];
            total_perp += exp(-s);
        }
        __syncthreads();
    }
    if (t == 0) {
        double tc = 0.0;
        for (int l = 0; l < LAYERS; l++)
            tc += g_loss[l] / ((double)N_TOK * (double)DIM);
        size_t off = (size_t)N_TOK * DIM + (size_t)LAYERS * N_TOK;
        out[off + 0] = (float)(0.25 * tc + tc);
        out[off + 1] = (float)tc;
        out[off + 2] = (float)tc;
        out[off + 3] = (float)(total_perp / (double)LAYERS);
    }
}

// ---------------- launch ----------------
extern "C" void kernel_launch(void* const* d_in, const int* in_sizes, int n_in,
                              void* d_out, int out_size) {
    const float* z  = (const float*)d_in[0];
    const float* cb = (const float*)d_in[1];
    float* out = (float*)d_out;

    cudaFuncSetAttribute(rvq_main_kernel,
                         cudaFuncAttributeMaxDynamicSharedMemorySize, SM_TOTAL);

    rvq_init_kernel<<<1, 256>>>();
    rvq_prep_kernel<<<(LAYERS * KCODES * 32 + 255) / 256, 256>>>(cb);
    rvq_main_kernel<<<N_TOK / TOKB, THREADS, SM_TOTAL>>>(z, cb, out);
    rvq_final_kernel<<<1, 256>>>(out);
}